// round 2
// baseline (speedup 1.0000x reference)
#include <cuda_runtime.h>
#include <cuda_bf16.h>
#include <math.h>

// Problem shape (fixed by setup_inputs): N=50000, H=256, E=300000.
// Strategy: g = MLP(emb) computed ONCE over all N nodes (exact — MLP is
// row-independent, so MLP(emb)[idx] == MLP(emb[idx]) bit-for-bit),
// then per-edge cosine = dot(g[col],g[row]) * inv_norm[col] * inv_norm[row].
//
// edge_index is int32 on the wire (JAX x64 disabled downcasts jnp.int64).

#define H256 256
#define NPAD 50176  // 392*128, covers N=50000

// Scratch (device globals — allocation-free per harness rules)
__device__ float g_h[(size_t)NPAD * H256];    // relu(emb @ W1^T + b1)
__device__ float g_g[(size_t)NPAD * H256];    // g_h @ W2^T + b2
__device__ float g_inv[NPAD];                 // 1 / max(||g||, eps)

// ---------------------------------------------------------------------------
// GEMM: C[n][o] = act( sum_k A[n][k] * W[o][k] + bias[o] ), H = 256
// NT layout (both A and W are K-contiguous). Tile 128x128x8, 256 threads,
// 8x8 register micro-tile per thread. FFMA:LDS = 2:1 → fma-pipe bound.
// ---------------------------------------------------------------------------
__global__ __launch_bounds__(256) void gemm256_nt(
    const float* __restrict__ A, const float* __restrict__ W,
    const float* __restrict__ bias, float* __restrict__ C,
    int N, int do_relu)
{
    __shared__ float As[8][128];
    __shared__ float Ws[8][128];

    const int tid  = threadIdx.x;          // 0..255
    const int row0 = blockIdx.x * 128;
    const int col0 = blockIdx.y * 128;

    // Loader mapping: each thread loads one float4 of A and one of W per k-tile.
    const int l_row = tid >> 1;            // 0..127
    const int l_k4  = (tid & 1) * 4;       // 0 or 4

    // Compute mapping: 16x16 thread grid, 8 rows x 8 cols each.
    const int tx = tid & 15;               // col group
    const int ty = tid >> 4;               // row group
    const int crow = ty * 8;
    const int ccol = tx * 8;

    float acc[8][8];
#pragma unroll
    for (int i = 0; i < 8; i++)
#pragma unroll
        for (int j = 0; j < 8; j++) acc[i][j] = 0.0f;

    const int a_row = row0 + l_row;
    const float* Aptr = A + (size_t)a_row * H256 + l_k4;
    const float* Wptr = W + (size_t)(col0 + l_row) * H256 + l_k4;
    const bool a_ok = (a_row < N);

    for (int kt = 0; kt < H256; kt += 8) {
        float4 av = a_ok ? *(const float4*)(Aptr + kt) : make_float4(0.f, 0.f, 0.f, 0.f);
        float4 wv = *(const float4*)(Wptr + kt);
        As[l_k4 + 0][l_row] = av.x;
        As[l_k4 + 1][l_row] = av.y;
        As[l_k4 + 2][l_row] = av.z;
        As[l_k4 + 3][l_row] = av.w;
        Ws[l_k4 + 0][l_row] = wv.x;
        Ws[l_k4 + 1][l_row] = wv.y;
        Ws[l_k4 + 2][l_row] = wv.z;
        Ws[l_k4 + 3][l_row] = wv.w;
        __syncthreads();

#pragma unroll
        for (int k = 0; k < 8; k++) {
            float4 a0 = *(const float4*)&As[k][crow];
            float4 a1 = *(const float4*)&As[k][crow + 4];
            float4 b0 = *(const float4*)&Ws[k][ccol];
            float4 b1 = *(const float4*)&Ws[k][ccol + 4];
            float a[8] = {a0.x, a0.y, a0.z, a0.w, a1.x, a1.y, a1.z, a1.w};
            float b[8] = {b0.x, b0.y, b0.z, b0.w, b1.x, b1.y, b1.z, b1.w};
#pragma unroll
            for (int i = 0; i < 8; i++)
#pragma unroll
                for (int j = 0; j < 8; j++)
                    acc[i][j] = fmaf(a[i], b[j], acc[i][j]);
        }
        __syncthreads();
    }

    // Epilogue: bias (+ReLU), store.
    float4 bia0 = *(const float4*)(bias + col0 + ccol);
    float4 bia1 = *(const float4*)(bias + col0 + ccol + 4);
    float bv[8] = {bia0.x, bia0.y, bia0.z, bia0.w, bia1.x, bia1.y, bia1.z, bia1.w};

#pragma unroll
    for (int i = 0; i < 8; i++) {
        int r = row0 + crow + i;
        if (r >= N) break;
        float out[8];
#pragma unroll
        for (int j = 0; j < 8; j++) {
            float v = acc[i][j] + bv[j];
            out[j] = do_relu ? fmaxf(v, 0.0f) : v;
        }
        float4* cp = (float4*)(C + (size_t)r * H256 + col0 + ccol);
        cp[0] = make_float4(out[0], out[1], out[2], out[3]);
        cp[1] = make_float4(out[4], out[5], out[6], out[7]);
    }
}

// ---------------------------------------------------------------------------
// Per-row inverse norm: inv[n] = 1 / max(||g[n]||, 1e-8). One warp per row.
// ---------------------------------------------------------------------------
__global__ __launch_bounds__(256) void rownorm_kernel(
    const float* __restrict__ g, float* __restrict__ inv, int N)
{
    int row  = blockIdx.x * 8 + (threadIdx.x >> 5);
    int lane = threadIdx.x & 31;
    if (row >= N) return;
    const float4* p = (const float4*)(g + (size_t)row * H256);
    float s = 0.0f;
#pragma unroll
    for (int i = 0; i < 2; i++) {
        float4 v = p[lane + i * 32];
        s = fmaf(v.x, v.x, s);
        s = fmaf(v.y, v.y, s);
        s = fmaf(v.z, v.z, s);
        s = fmaf(v.w, v.w, s);
    }
#pragma unroll
    for (int o = 16; o; o >>= 1) s += __shfl_xor_sync(0xffffffffu, s, o);
    if (lane == 0) inv[row] = 1.0f / fmaxf(sqrtf(s), 1e-8f);
}

// ---------------------------------------------------------------------------
// Edge kernel: one warp per edge. g rows live in L2 (51.2 MB < 126 MB).
// out[e] = dot(g[col],g[row]) * inv[col] * inv[row]
// Indices are int32; clamp defensively so a dtype surprise shows up as
// rel_err, not an illegal access.
// ---------------------------------------------------------------------------
__global__ __launch_bounds__(256) void edge_kernel(
    const float* __restrict__ g, const float* __restrict__ inv,
    const int* __restrict__ ei, float* __restrict__ out, int E, int N)
{
    int e    = blockIdx.x * 8 + (threadIdx.x >> 5);
    int lane = threadIdx.x & 31;
    if (e >= E) return;
    int c = ei[e];
    int r = ei[E + e];
    c = min(max(c, 0), N - 1);
    r = min(max(r, 0), N - 1);
    const float4* p1 = (const float4*)(g + (size_t)c * H256);
    const float4* p2 = (const float4*)(g + (size_t)r * H256);
    float s = 0.0f;
#pragma unroll
    for (int i = 0; i < 2; i++) {
        float4 a = p1[lane + i * 32];
        float4 b = p2[lane + i * 32];
        s = fmaf(a.x, b.x, s);
        s = fmaf(a.y, b.y, s);
        s = fmaf(a.z, b.z, s);
        s = fmaf(a.w, b.w, s);
    }
#pragma unroll
    for (int o = 16; o; o >>= 1) s += __shfl_xor_sync(0xffffffffu, s, o);
    if (lane == 0) out[e] = s * inv[c] * inv[r];
}

// ---------------------------------------------------------------------------
extern "C" void kernel_launch(void* const* d_in, const int* in_sizes, int n_in,
                              void* d_out, int out_size)
{
    const float* emb = (const float*)d_in[0];
    const int*   ei  = (const int*)d_in[1];
    const float* W1  = (const float*)d_in[2];
    const float* b1  = (const float*)d_in[3];
    const float* W2  = (const float*)d_in[4];
    const float* b2  = (const float*)d_in[5];
    float*       out = (float*)d_out;

    const int Hn = in_sizes[3];          // 256
    const int N  = in_sizes[0] / Hn;     // 50000
    const int E  = in_sizes[1] / 2;      // 300000
    if (Hn != H256 || N > NPAD) return;

    float *hbuf, *gbuf, *invbuf;
    cudaGetSymbolAddress((void**)&hbuf, g_h);
    cudaGetSymbolAddress((void**)&gbuf, g_g);
    cudaGetSymbolAddress((void**)&invbuf, g_inv);

    dim3 ggrid((N + 127) / 128, H256 / 128);
    // Layer 1: h = relu(emb @ W1^T + b1)
    gemm256_nt<<<ggrid, 256>>>(emb, W1, b1, hbuf, N, 1);
    // Layer 2: g = h @ W2^T + b2
    gemm256_nt<<<ggrid, 256>>>(hbuf, W2, b2, gbuf, N, 0);
    // Row inverse norms
    rownorm_kernel<<<(N + 7) / 8, 256>>>(gbuf, invbuf, N);
    // Per-edge cosine
    edge_kernel<<<(E + 7) / 8, 256>>>(gbuf, invbuf, ei, out, E, N);
}

// round 5
// speedup vs baseline: 1.9280x; 1.9280x over previous
#include <cuda_runtime.h>
#include <cuda_bf16.h>
#include <cstdint>
#include <math.h>

// N=50000, H=256, E=300000.
// g = MLP(emb) once over nodes (exact restructure), per-edge cosine gather.
// GEMMs: warp-level HMMA (mma.sync bf16, baseline compute_103 PTX — tcgen05
// is sm_103a-only and this harness compiles without the 'a' feature set).
// Split precision: x = x_hi + x_lo (bf16 each); keep 3 of 4 cross products.

#define H256 256
#define NPAD 50176  // 392*128

// ---------------- device scratch (allocation-free) ----------------
__device__ __align__(16) float          g_g[(size_t)NPAD * H256];
__device__ __align__(16) __nv_bfloat16  g_e_hi[(size_t)NPAD * H256];
__device__ __align__(16) __nv_bfloat16  g_e_lo[(size_t)NPAD * H256];
__device__ __align__(16) __nv_bfloat16  g_h_hi[(size_t)NPAD * H256];
__device__ __align__(16) __nv_bfloat16  g_h_lo[(size_t)NPAD * H256];
__device__ __align__(16) __nv_bfloat16  g_w1_hi[H256 * H256];
__device__ __align__(16) __nv_bfloat16  g_w1_lo[H256 * H256];
__device__ __align__(16) __nv_bfloat16  g_w2_hi[H256 * H256];
__device__ __align__(16) __nv_bfloat16  g_w2_lo[H256 * H256];
__device__ float g_inv[NPAD];

// ---------------- PTX helpers (all baseline sm_80-class) ----------------
__device__ __forceinline__ uint32_t smem_u32(const void* p) {
    uint32_t a;
    asm("{ .reg .u64 t; cvta.to.shared.u64 t, %1; cvt.u32.u64 %0, t; }" : "=r"(a) : "l"(p));
    return a;
}
__device__ __forceinline__ void cp16(uint32_t s, const void* g) {
    asm volatile("cp.async.cg.shared.global [%0], [%1], 16;"
                 :: "r"(s), "l"(__cvta_generic_to_global(g)) : "memory");
}
__device__ __forceinline__ void cp_commit() {
    asm volatile("cp.async.commit_group;" ::: "memory");
}
template <int NN>
__device__ __forceinline__ void cp_wait() {
    asm volatile("cp.async.wait_group %0;" :: "n"(NN) : "memory");
}
__device__ __forceinline__ void ldsm4(uint32_t* r, uint32_t addr) {
    asm volatile("ldmatrix.sync.aligned.m8n8.x4.shared.b16 {%0,%1,%2,%3}, [%4];"
                 : "=r"(r[0]), "=r"(r[1]), "=r"(r[2]), "=r"(r[3]) : "r"(addr));
}
__device__ __forceinline__ void mma_bf16(float* c, const uint32_t* a, const uint32_t* b) {
    asm volatile(
        "mma.sync.aligned.m16n8k16.row.col.f32.bf16.bf16.f32 "
        "{%0,%1,%2,%3}, {%4,%5,%6,%7}, {%8,%9}, {%0,%1,%2,%3};"
        : "+f"(c[0]), "+f"(c[1]), "+f"(c[2]), "+f"(c[3])
        : "r"(a[0]), "r"(a[1]), "r"(a[2]), "r"(a[3]), "r"(b[0]), "r"(b[1]));
}
__device__ __forceinline__ uint32_t pack_bf2(float a, float b) {
    __nv_bfloat162 t = __floats2bfloat162_rn(a, b);
    return *reinterpret_cast<uint32_t*>(&t);
}

// SMEM tile: 128 rows x 64 k-elems bf16 = 128B/row, XOR swizzle on bits[6:4]^rowlow.
// off(r,kbyte) = r*128 + (kbyte ^ ((r&7)<<4))
#define ST_A_HI 0
#define ST_A_LO 16384
#define ST_B_HI 32768
#define ST_B_LO 49152
#define STAGE_BYTES 65536
#define SMEM_BYTES (2 * STAGE_BYTES)

// ---------------------------------------------------------------------------
// HMMA split-bf16 GEMM: C[128,128] tile/CTA, 256 thr (8 warps, 2m x 4n of 64x32).
// K=256 in 4 chunks of 64, cp.async double-buffered.
// mode 0: out = relu(C+bias) split to bf16 hi/lo;  mode 1: out = fp32 C+bias.
// ---------------------------------------------------------------------------
__global__ __launch_bounds__(256, 1) void gemm_hmma(
    const __nv_bfloat16* __restrict__ Ahi, const __nv_bfloat16* __restrict__ Alo,
    const __nv_bfloat16* __restrict__ Bhi, const __nv_bfloat16* __restrict__ Blo,
    const float* __restrict__ bias, int mode,
    __nv_bfloat16* __restrict__ OutHi, __nv_bfloat16* __restrict__ OutLo,
    float* __restrict__ OutF)
{
    extern __shared__ char smem[];
    const uint32_t sb = smem_u32(smem);
    const int tid  = threadIdx.x;
    const int lane = tid & 31, wid = tid >> 5;
    const int wm = wid & 1, wn = wid >> 1;        // 2 x 4 warp grid
    const int row0 = blockIdx.x * 128;
    const int col0 = blockIdx.y * 128;

    float C[4][4][4];
#pragma unroll
    for (int i = 0; i < 4; i++)
#pragma unroll
        for (int j = 0; j < 4; j++)
#pragma unroll
            for (int q = 0; q < 4; q++) C[i][j][q] = 0.0f;

    // ---- ldmatrix lane-address precompute ----
    // A quadrant order: (r0-7,k0),(r8-15,k0),(r0-7,k8),(r8-15,k8)
    const int a_r  = wm * 64 + (lane & 7) + ((lane >> 3) & 1) * 8;  // + i*16
    const int a_kq = ((lane >> 4) & 1) * 8;
    // B quadrant order: (n0-7,k0),(n0-7,k8),(n8-15,k0),(n8-15,k8)
    const int b_n  = wn * 32 + (lane & 7) + ((lane >> 4) & 1) * 8;  // + j*16
    const int b_kq = ((lane >> 3) & 1) * 8;

    uint32_t aRow[4], aMask[4], bRow[2], bMask[2];
#pragma unroll
    for (int i = 0; i < 4; i++) {
        int r = a_r + i * 16;
        aRow[i]  = (uint32_t)(r * 128);
        aMask[i] = (uint32_t)((r & 7) << 4);
    }
#pragma unroll
    for (int j = 0; j < 2; j++) {
        int n = b_n + j * 16;
        bRow[j]  = (uint32_t)(n * 128);
        bMask[j] = (uint32_t)((n & 7) << 4);
    }

    // ---- cp.async loader lambda (stage st, K-chunk kc) ----
    auto load_stage = [&](int st, int kc) {
        uint32_t base = sb + st * STAGE_BYTES;
        const int kofs = kc * 64;
#pragma unroll
        for (int it = 0; it < 4; it++) {
            int idx = tid + it * 256;          // 0..1023
            int r   = idx >> 3;
            int c8  = idx & 7;                 // 16B chunk (8 bf16)
            uint32_t so = (uint32_t)(r * 128 + ((c8 * 16) ^ ((r & 7) << 4)));
            size_t ga = (size_t)(row0 + r) * H256 + kofs + c8 * 8;
            size_t gb = (size_t)(col0 + r) * H256 + kofs + c8 * 8;
            cp16(base + ST_A_HI + so, Ahi + ga);
            cp16(base + ST_A_LO + so, Alo + ga);
            cp16(base + ST_B_HI + so, Bhi + gb);
            cp16(base + ST_B_LO + so, Blo + gb);
        }
    };

    load_stage(0, 0);
    cp_commit();

#pragma unroll
    for (int kc = 0; kc < 4; kc++) {
        if (kc < 3) {
            load_stage((kc + 1) & 1, kc + 1);
            cp_commit();
            cp_wait<1>();
        } else {
            cp_wait<0>();
        }
        __syncthreads();

        const uint32_t base = sb + (kc & 1) * STAGE_BYTES;
#pragma unroll
        for (int s = 0; s < 4; s++) {
            const int k0 = s * 16;
            uint32_t ah[4][4], al[4][4], bh[2][4], bl[2][4];
#pragma unroll
            for (int i = 0; i < 4; i++) {
                uint32_t ko = (uint32_t)((k0 + a_kq) * 2);
                uint32_t off = aRow[i] + (ko ^ aMask[i]);
                ldsm4(ah[i], base + ST_A_HI + off);
                ldsm4(al[i], base + ST_A_LO + off);
            }
#pragma unroll
            for (int j = 0; j < 2; j++) {
                uint32_t ko = (uint32_t)((k0 + b_kq) * 2);
                uint32_t off = bRow[j] + (ko ^ bMask[j]);
                ldsm4(bh[j], base + ST_B_HI + off);
                ldsm4(bl[j], base + ST_B_LO + off);
            }
#pragma unroll
            for (int i = 0; i < 4; i++)
#pragma unroll
                for (int j = 0; j < 2; j++)
#pragma unroll
                    for (int h = 0; h < 2; h++) {
                        const int ns = j * 2 + h;
                        mma_bf16(C[i][ns], ah[i], &bh[j][2 * h]);
                        mma_bf16(C[i][ns], ah[i], &bl[j][2 * h]);
                        mma_bf16(C[i][ns], al[i], &bh[j][2 * h]);
                    }
        }
        __syncthreads();
    }

    // ---- Epilogue ----
    const int rbase = row0 + wm * 64 + (lane >> 2);
    const int cbase = col0 + wn * 32 + (lane & 3) * 2;
#pragma unroll
    for (int i = 0; i < 4; i++) {
#pragma unroll
        for (int ns = 0; ns < 4; ns++) {
            const int c  = cbase + ns * 8;
            const float bv0 = __ldg(&bias[c]);
            const float bv1 = __ldg(&bias[c + 1]);
#pragma unroll
            for (int rh = 0; rh < 2; rh++) {
                const int r = rbase + i * 16 + rh * 8;
                float v0 = C[i][ns][rh * 2 + 0] + bv0;
                float v1 = C[i][ns][rh * 2 + 1] + bv1;
                const size_t go = (size_t)r * H256 + c;
                if (mode == 0) {
                    v0 = fmaxf(v0, 0.0f);
                    v1 = fmaxf(v1, 0.0f);
                    float h0 = __bfloat162float(__float2bfloat16_rn(v0));
                    float h1 = __bfloat162float(__float2bfloat16_rn(v1));
                    *(uint32_t*)(OutHi + go) = pack_bf2(h0, h1);
                    *(uint32_t*)(OutLo + go) = pack_bf2(v0 - h0, v1 - h1);
                } else {
                    *(float2*)(OutF + go) = make_float2(v0, v1);
                }
            }
        }
    }
}

// ---------------------------------------------------------------------------
// Prep: split emb and W1/W2 into bf16 hi/lo.
// ---------------------------------------------------------------------------
__global__ __launch_bounds__(256) void prep_kernel(
    const float* __restrict__ emb, const float* __restrict__ W1,
    const float* __restrict__ W2, int n_emb,
    __nv_bfloat16* ehi, __nv_bfloat16* elo,
    __nv_bfloat16* w1h, __nv_bfloat16* w1l,
    __nv_bfloat16* w2h, __nv_bfloat16* w2l)
{
    int i = blockIdx.x * 256 + threadIdx.x;
    if (i < n_emb) {
        float a = emb[i];
        __nv_bfloat16 h = __float2bfloat16_rn(a);
        ehi[i] = h;
        elo[i] = __float2bfloat16_rn(a - __bfloat162float(h));
    }
    if (i < H256 * H256) {
        float a = W1[i];
        __nv_bfloat16 h = __float2bfloat16_rn(a);
        w1h[i] = h;
        w1l[i] = __float2bfloat16_rn(a - __bfloat162float(h));
        float b = W2[i];
        __nv_bfloat16 h2 = __float2bfloat16_rn(b);
        w2h[i] = h2;
        w2l[i] = __float2bfloat16_rn(b - __bfloat162float(h2));
    }
}

// ---------------------------------------------------------------------------
// Row inverse norm (deterministic, one warp per row).
// ---------------------------------------------------------------------------
__global__ __launch_bounds__(256) void rownorm_kernel(
    const float* __restrict__ g, float* __restrict__ inv, int N)
{
    int row  = blockIdx.x * 8 + (threadIdx.x >> 5);
    int lane = threadIdx.x & 31;
    if (row >= N) return;
    const float4* p = (const float4*)(g + (size_t)row * H256);
    float s = 0.0f;
#pragma unroll
    for (int i = 0; i < 2; i++) {
        float4 v = p[lane + i * 32];
        s = fmaf(v.x, v.x, s); s = fmaf(v.y, v.y, s);
        s = fmaf(v.z, v.z, s); s = fmaf(v.w, v.w, s);
    }
#pragma unroll
    for (int o = 16; o; o >>= 1) s += __shfl_xor_sync(0xffffffffu, s, o);
    if (lane == 0) inv[row] = 1.0f / fmaxf(sqrtf(s), 1e-8f);
}

// ---------------------------------------------------------------------------
// Edge kernel: one warp per edge; g rows are L2-resident (51 MB).
// ---------------------------------------------------------------------------
__global__ __launch_bounds__(256) void edge_kernel(
    const float* __restrict__ g, const float* __restrict__ inv,
    const int* __restrict__ ei, float* __restrict__ out, int E, int N)
{
    int e    = blockIdx.x * 8 + (threadIdx.x >> 5);
    int lane = threadIdx.x & 31;
    if (e >= E) return;
    int c = ei[e];
    int r = ei[E + e];
    c = min(max(c, 0), N - 1);
    r = min(max(r, 0), N - 1);
    const float4* p1 = (const float4*)(g + (size_t)c * H256);
    const float4* p2 = (const float4*)(g + (size_t)r * H256);
    float s = 0.0f;
#pragma unroll
    for (int i = 0; i < 2; i++) {
        float4 a = p1[lane + i * 32];
        float4 b = p2[lane + i * 32];
        s = fmaf(a.x, b.x, s); s = fmaf(a.y, b.y, s);
        s = fmaf(a.z, b.z, s); s = fmaf(a.w, b.w, s);
    }
#pragma unroll
    for (int o = 16; o; o >>= 1) s += __shfl_xor_sync(0xffffffffu, s, o);
    if (lane == 0) out[e] = s * inv[c] * inv[r];
}

// ---------------------------------------------------------------------------
extern "C" void kernel_launch(void* const* d_in, const int* in_sizes, int n_in,
                              void* d_out, int out_size)
{
    const float* emb = (const float*)d_in[0];
    const int*   ei  = (const int*)d_in[1];
    const float* W1  = (const float*)d_in[2];
    const float* b1  = (const float*)d_in[3];
    const float* W2  = (const float*)d_in[4];
    const float* b2  = (const float*)d_in[5];
    float*       out = (float*)d_out;

    const int Hn = in_sizes[3];
    const int N  = in_sizes[0] / Hn;
    const int E  = in_sizes[1] / 2;
    if (Hn != H256 || N > NPAD) return;

    float *gbuf, *invbuf;
    __nv_bfloat16 *ehi, *elo, *hhi, *hlo, *w1h, *w1l, *w2h, *w2l;
    cudaGetSymbolAddress((void**)&gbuf, g_g);
    cudaGetSymbolAddress((void**)&ehi,  g_e_hi);
    cudaGetSymbolAddress((void**)&elo,  g_e_lo);
    cudaGetSymbolAddress((void**)&hhi,  g_h_hi);
    cudaGetSymbolAddress((void**)&hlo,  g_h_lo);
    cudaGetSymbolAddress((void**)&w1h,  g_w1_hi);
    cudaGetSymbolAddress((void**)&w1l,  g_w1_lo);
    cudaGetSymbolAddress((void**)&w2h,  g_w2_hi);
    cudaGetSymbolAddress((void**)&w2l,  g_w2_lo);
    cudaGetSymbolAddress((void**)&invbuf, g_inv);

    cudaFuncSetAttribute(gemm_hmma, cudaFuncAttributeMaxDynamicSharedMemorySize, SMEM_BYTES);

    const int n_emb = N * H256;
    prep_kernel<<<(n_emb + 255) / 256, 256>>>(emb, W1, W2, n_emb,
                                              ehi, elo, w1h, w1l, w2h, w2l);

    dim3 ggrid(NPAD / 128, 2);
    // Layer 1: h = relu(emb @ W1^T + b1), stored pre-split bf16 hi/lo
    gemm_hmma<<<ggrid, 256, SMEM_BYTES>>>(ehi, elo, w1h, w1l, b1, 0,
                                          hhi, hlo, nullptr);
    // Layer 2: g = h @ W2^T + b2, fp32
    gemm_hmma<<<ggrid, 256, SMEM_BYTES>>>(hhi, hlo, w2h, w2l, b2, 1,
                                          nullptr, nullptr, gbuf);
    rownorm_kernel<<<(N + 7) / 8, 256>>>(gbuf, invbuf, N);
    edge_kernel<<<(E + 7) / 8, 256>>>(gbuf, invbuf, ei, out, E, N);
}

// round 6
// speedup vs baseline: 2.0751x; 1.0763x over previous
#include <cuda_runtime.h>
#include <cuda_bf16.h>
#include <cstdint>
#include <math.h>

// N=50000, H=256, E=300000.
// g = MLP(emb) once over nodes (exact restructure), per-edge cosine gather.
// GEMMs: warp-level HMMA (mma.sync bf16, baseline compute_103 PTX).
// Split precision: x = x_hi + x_lo (bf16); keep hh, hl, lh products.
// Layer1 splits fp32 emb on the fly; layer2 fuses row-sumsq into epilogue.

#define H256 256
#define NPAD 50176  // 392*128

// ---------------- device scratch (allocation-free) ----------------
__device__ __align__(16) float          g_g[(size_t)NPAD * H256];
__device__ __align__(16) __nv_bfloat16  g_h_hi[(size_t)NPAD * H256];
__device__ __align__(16) __nv_bfloat16  g_h_lo[(size_t)NPAD * H256];
__device__ __align__(16) __nv_bfloat16  g_w1_hi[H256 * H256];
__device__ __align__(16) __nv_bfloat16  g_w1_lo[H256 * H256];
__device__ __align__(16) __nv_bfloat16  g_w2_hi[H256 * H256];
__device__ __align__(16) __nv_bfloat16  g_w2_lo[H256 * H256];
__device__ float g_sumsq[NPAD];
__device__ float g_inv[NPAD];

// ---------------- PTX helpers ----------------
__device__ __forceinline__ uint32_t smem_u32(const void* p) {
    uint32_t a;
    asm("{ .reg .u64 t; cvta.to.shared.u64 t, %1; cvt.u32.u64 %0, t; }" : "=r"(a) : "l"(p));
    return a;
}
__device__ __forceinline__ void cp16(uint32_t s, const void* g) {
    asm volatile("cp.async.cg.shared.global [%0], [%1], 16;"
                 :: "r"(s), "l"(__cvta_generic_to_global(g)) : "memory");
}
__device__ __forceinline__ void cp_commit() {
    asm volatile("cp.async.commit_group;" ::: "memory");
}
template <int NN>
__device__ __forceinline__ void cp_wait() {
    asm volatile("cp.async.wait_group %0;" :: "n"(NN) : "memory");
}
__device__ __forceinline__ void ldsm4(uint32_t* r, uint32_t addr) {
    asm volatile("ldmatrix.sync.aligned.m8n8.x4.shared.b16 {%0,%1,%2,%3}, [%4];"
                 : "=r"(r[0]), "=r"(r[1]), "=r"(r[2]), "=r"(r[3]) : "r"(addr));
}
__device__ __forceinline__ void mma_bf16(float* c, const uint32_t* a, const uint32_t* b) {
    asm volatile(
        "mma.sync.aligned.m16n8k16.row.col.f32.bf16.bf16.f32 "
        "{%0,%1,%2,%3}, {%4,%5,%6,%7}, {%8,%9}, {%0,%1,%2,%3};"
        : "+f"(c[0]), "+f"(c[1]), "+f"(c[2]), "+f"(c[3])
        : "r"(a[0]), "r"(a[1]), "r"(a[2]), "r"(a[3]), "r"(b[0]), "r"(b[1]));
}
__device__ __forceinline__ uint32_t pack_bf2(float a, float b) {
    __nv_bfloat162 t = __floats2bfloat162_rn(a, b);
    return *reinterpret_cast<uint32_t*>(&t);
}

// SMEM: B (full K=256, 4 chunk-tiles of 128rx64k, 128B/row XOR-swizzled),
//       A double-buffered per 64-k chunk.
#define OFF_B_HI 0
#define OFF_B_LO 65536
#define OFF_A_HI 131072
#define OFF_A_LO 163840
#define SMEM_BYTES 196608

// ---------------------------------------------------------------------------
// HMMA split-bf16 GEMM: C[128,128] tile/CTA, 256 thr (8 warps, 2m x 4n, 64x32).
// mode 0: A = fp32 (split on the fly); out = relu(C+bias) split bf16 hi/lo.
// mode 1: A = bf16 hi/lo; out = fp32 C+bias, fused row sumsq.
// ---------------------------------------------------------------------------
__global__ __launch_bounds__(256, 1) void gemm_hmma(
    const float* __restrict__ A32,
    const __nv_bfloat16* __restrict__ Ahi, const __nv_bfloat16* __restrict__ Alo,
    const __nv_bfloat16* __restrict__ Bhi, const __nv_bfloat16* __restrict__ Blo,
    const float* __restrict__ bias, int Nn, int mode,
    __nv_bfloat16* __restrict__ OutHi, __nv_bfloat16* __restrict__ OutLo,
    float* __restrict__ OutF, float* __restrict__ sumsq)
{
    extern __shared__ char smem[];
    const uint32_t sb = smem_u32(smem);
    const int tid  = threadIdx.x;
    const int lane = tid & 31, wid = tid >> 5;
    const int wm = wid & 1, wn = wid >> 1;        // 2 x 4 warp grid
    const int row0 = blockIdx.x * 128;
    const int col0 = blockIdx.y * 128;

    float C[4][4][4];
#pragma unroll
    for (int i = 0; i < 4; i++)
#pragma unroll
        for (int j = 0; j < 4; j++)
#pragma unroll
            for (int q = 0; q < 4; q++) C[i][j][q] = 0.0f;

    // ---- ldmatrix lane addressing (within a 128-row x 64-k chunk tile) ----
    const int a_r  = wm * 64 + (lane & 7) + ((lane >> 3) & 1) * 8;
    const int a_kq = ((lane >> 4) & 1) * 8;
    const int b_n  = wn * 32 + (lane & 7) + ((lane >> 4) & 1) * 8;
    const int b_kq = ((lane >> 3) & 1) * 8;
    uint32_t aRow[4], aMask[4], bRow[2], bMask[2];
#pragma unroll
    for (int i = 0; i < 4; i++) {
        int r = a_r + i * 16;
        aRow[i]  = (uint32_t)(r * 128);
        aMask[i] = (uint32_t)((r & 7) << 4);
    }
#pragma unroll
    for (int j = 0; j < 2; j++) {
        int n = b_n + j * 16;
        bRow[j]  = (uint32_t)(n * 128);
        bMask[j] = (uint32_t)((n & 7) << 4);
    }

    // ---- B: full K=256 tile via cp.async (one time) ----
#pragma unroll
    for (int it = 0; it < 16; it++) {
        int idx = tid + it * 256;              // 0..4095
        int r   = idx >> 5;
        int c8  = idx & 31;
        uint32_t off = (uint32_t)((c8 >> 3) * 16384 + r * 128 +
                                  (((c8 & 7) * 16) ^ ((r & 7) << 4)));
        size_t gb = (size_t)(col0 + r) * H256 + c8 * 8;
        cp16(sb + OFF_B_HI + off, Bhi + gb);
        cp16(sb + OFF_B_LO + off, Blo + gb);
    }
    cp_commit();

    float4 regs[8];
    if (mode == 0) {
        // preload chunk 0 (fp32, guarded)
#pragma unroll
        for (int it = 0; it < 8; it++) {
            int idx = tid + it * 256;
            int r = idx >> 4, k4 = (idx & 15) * 4;
            regs[it] = (row0 + r < Nn)
                ? *(const float4*)(A32 + (size_t)(row0 + r) * H256 + k4)
                : make_float4(0.f, 0.f, 0.f, 0.f);
        }
    } else {
#pragma unroll
        for (int it = 0; it < 4; it++) {
            int idx = tid + it * 256;          // 0..1023
            int r = idx >> 3, c8 = idx & 7;
            uint32_t off = (uint32_t)(r * 128 + ((c8 * 16) ^ ((r & 7) << 4)));
            size_t ga = (size_t)(row0 + r) * H256 + c8 * 8;
            cp16(sb + OFF_A_HI + off, Ahi + ga);
            cp16(sb + OFF_A_LO + off, Alo + ga);
        }
        cp_commit();
    }

#pragma unroll
    for (int kc = 0; kc < 4; kc++) {
        const uint32_t st = (uint32_t)((kc & 1) * 16384);
        if (mode == 0) {
            // store current regs (chunk kc) as split bf16
#pragma unroll
            for (int it = 0; it < 8; it++) {
                int idx = tid + it * 256;
                int r = idx >> 4, k4 = (idx & 15) * 4;
                float4 v = regs[it];
                float h0 = __bfloat162float(__float2bfloat16_rn(v.x));
                float h1 = __bfloat162float(__float2bfloat16_rn(v.y));
                float h2 = __bfloat162float(__float2bfloat16_rn(v.z));
                float h3 = __bfloat162float(__float2bfloat16_rn(v.w));
                uint32_t off = (uint32_t)(r * 128 + ((k4 * 2) ^ ((r & 7) << 4)));
                *(uint2*)(smem + OFF_A_HI + st + off) =
                    make_uint2(pack_bf2(h0, h1), pack_bf2(h2, h3));
                *(uint2*)(smem + OFF_A_LO + st + off) =
                    make_uint2(pack_bf2(v.x - h0, v.y - h1), pack_bf2(v.z - h2, v.w - h3));
            }
            if (kc == 0) cp_wait<0>();         // B ready
            __syncthreads();
            if (kc < 3) {                      // issue next chunk's loads (overlap MMA)
#pragma unroll
                for (int it = 0; it < 8; it++) {
                    int idx = tid + it * 256;
                    int r = idx >> 4, k4 = (idx & 15) * 4;
                    regs[it] = (row0 + r < Nn)
                        ? *(const float4*)(A32 + (size_t)(row0 + r) * H256 + (kc + 1) * 64 + k4)
                        : make_float4(0.f, 0.f, 0.f, 0.f);
                }
            }
        } else {
            if (kc < 3) {
                const uint32_t st2 = (uint32_t)(((kc + 1) & 1) * 16384);
#pragma unroll
                for (int it = 0; it < 4; it++) {
                    int idx = tid + it * 256;
                    int r = idx >> 3, c8 = idx & 7;
                    uint32_t off = (uint32_t)(r * 128 + ((c8 * 16) ^ ((r & 7) << 4)));
                    size_t ga = (size_t)(row0 + r) * H256 + (kc + 1) * 64 + c8 * 8;
                    cp16(sb + OFF_A_HI + st2 + off, Ahi + ga);
                    cp16(sb + OFF_A_LO + st2 + off, Alo + ga);
                }
                cp_commit();
                cp_wait<1>();
            } else {
                cp_wait<0>();
            }
            __syncthreads();
        }

        const uint32_t aHiB = sb + OFF_A_HI + st;
        const uint32_t aLoB = sb + OFF_A_LO + st;
        const uint32_t bHiB = sb + OFF_B_HI + (uint32_t)(kc * 16384);
        const uint32_t bLoB = sb + OFF_B_LO + (uint32_t)(kc * 16384);
#pragma unroll
        for (int s = 0; s < 4; s++) {
            const int k0 = s * 16;
            uint32_t ah[4][4], al[4][4], bh[2][4], bl[2][4];
#pragma unroll
            for (int i = 0; i < 4; i++) {
                uint32_t ko  = (uint32_t)((k0 + a_kq) * 2);
                uint32_t off = aRow[i] + (ko ^ aMask[i]);
                ldsm4(ah[i], aHiB + off);
                ldsm4(al[i], aLoB + off);
            }
#pragma unroll
            for (int j = 0; j < 2; j++) {
                uint32_t ko  = (uint32_t)((k0 + b_kq) * 2);
                uint32_t off = bRow[j] + (ko ^ bMask[j]);
                ldsm4(bh[j], bHiB + off);
                ldsm4(bl[j], bLoB + off);
            }
#pragma unroll
            for (int i = 0; i < 4; i++)
#pragma unroll
                for (int j = 0; j < 2; j++)
#pragma unroll
                    for (int h = 0; h < 2; h++) {
                        const int ns = j * 2 + h;
                        mma_bf16(C[i][ns], ah[i], &bh[j][2 * h]);
                        mma_bf16(C[i][ns], ah[i], &bl[j][2 * h]);
                        mma_bf16(C[i][ns], al[i], &bh[j][2 * h]);
                    }
        }
        __syncthreads();
    }

    // ---- Epilogue ----
    const int rbase = row0 + wm * 64 + (lane >> 2);
    const int cbase = col0 + wn * 32 + (lane & 3) * 2;
    float ss[4][2];
#pragma unroll
    for (int i = 0; i < 4; i++) { ss[i][0] = 0.f; ss[i][1] = 0.f; }

#pragma unroll
    for (int i = 0; i < 4; i++) {
#pragma unroll
        for (int ns = 0; ns < 4; ns++) {
            const int c   = cbase + ns * 8;
            const float bv0 = __ldg(&bias[c]);
            const float bv1 = __ldg(&bias[c + 1]);
#pragma unroll
            for (int rh = 0; rh < 2; rh++) {
                const int r = rbase + i * 16 + rh * 8;
                float v0 = C[i][ns][rh * 2 + 0] + bv0;
                float v1 = C[i][ns][rh * 2 + 1] + bv1;
                const size_t go = (size_t)r * H256 + c;
                if (mode == 0) {
                    v0 = fmaxf(v0, 0.0f);
                    v1 = fmaxf(v1, 0.0f);
                    float h0 = __bfloat162float(__float2bfloat16_rn(v0));
                    float h1 = __bfloat162float(__float2bfloat16_rn(v1));
                    *(uint32_t*)(OutHi + go) = pack_bf2(h0, h1);
                    *(uint32_t*)(OutLo + go) = pack_bf2(v0 - h0, v1 - h1);
                } else {
                    *(float2*)(OutF + go) = make_float2(v0, v1);
                    ss[i][rh] = fmaf(v0, v0, ss[i][rh]);
                    ss[i][rh] = fmaf(v1, v1, ss[i][rh]);
                }
            }
        }
    }

    if (mode == 1) {
        // Deterministic in-CTA row reduction, then one atomicAdd per row per
        // CTA (2 commutative contributors per row across blockIdx.y).
        float* red = (float*)smem;   // 128 rows x 4 warps-per-row
#pragma unroll
        for (int i = 0; i < 4; i++)
#pragma unroll
            for (int rh = 0; rh < 2; rh++) {
                float s = ss[i][rh];
                s += __shfl_xor_sync(0xffffffffu, s, 1);
                s += __shfl_xor_sync(0xffffffffu, s, 2);
                int rl = wm * 64 + (lane >> 2) + i * 16 + rh * 8;
                if ((lane & 3) == 0) red[rl * 4 + wn] = s;
            }
        __syncthreads();
        if (tid < 128) {
            float s = ((red[tid * 4] + red[tid * 4 + 1]) + red[tid * 4 + 2]) + red[tid * 4 + 3];
            atomicAdd(&sumsq[row0 + tid], s);
        }
    }
}

// ---------------------------------------------------------------------------
// Prep: split W1/W2 into bf16 hi/lo; zero sumsq.
// ---------------------------------------------------------------------------
__global__ __launch_bounds__(256) void prep_w(
    const float* __restrict__ W1, const float* __restrict__ W2,
    __nv_bfloat16* w1h, __nv_bfloat16* w1l,
    __nv_bfloat16* w2h, __nv_bfloat16* w2l, float* ss)
{
    int i = blockIdx.x * 256 + threadIdx.x;
    if (i < H256 * H256) {
        float a = W1[i];
        __nv_bfloat16 h = __float2bfloat16_rn(a);
        w1h[i] = h;
        w1l[i] = __float2bfloat16_rn(a - __bfloat162float(h));
        float b = W2[i];
        __nv_bfloat16 h2 = __float2bfloat16_rn(b);
        w2h[i] = h2;
        w2l[i] = __float2bfloat16_rn(b - __bfloat162float(h2));
    }
    if (i < NPAD) ss[i] = 0.0f;
}

__global__ __launch_bounds__(256) void finish_inv(
    const float* __restrict__ ss, float* __restrict__ inv, int n)
{
    int i = blockIdx.x * 256 + threadIdx.x;
    if (i < n) inv[i] = 1.0f / fmaxf(sqrtf(ss[i]), 1e-8f);
}

// ---------------------------------------------------------------------------
// Edge kernel: one warp per edge; g rows L2-resident (51 MB). At LTS cap.
// ---------------------------------------------------------------------------
__global__ __launch_bounds__(256) void edge_kernel(
    const float* __restrict__ g, const float* __restrict__ inv,
    const int* __restrict__ ei, float* __restrict__ out, int E, int N)
{
    int e    = blockIdx.x * 8 + (threadIdx.x >> 5);
    int lane = threadIdx.x & 31;
    if (e >= E) return;
    int c = ei[e];
    int r = ei[E + e];
    c = min(max(c, 0), N - 1);
    r = min(max(r, 0), N - 1);
    const float4* p1 = (const float4*)(g + (size_t)c * H256);
    const float4* p2 = (const float4*)(g + (size_t)r * H256);
    float s = 0.0f;
#pragma unroll
    for (int i = 0; i < 2; i++) {
        float4 a = p1[lane + i * 32];
        float4 b = p2[lane + i * 32];
        s = fmaf(a.x, b.x, s); s = fmaf(a.y, b.y, s);
        s = fmaf(a.z, b.z, s); s = fmaf(a.w, b.w, s);
    }
#pragma unroll
    for (int o = 16; o; o >>= 1) s += __shfl_xor_sync(0xffffffffu, s, o);
    if (lane == 0) out[e] = s * inv[c] * inv[r];
}

// ---------------------------------------------------------------------------
extern "C" void kernel_launch(void* const* d_in, const int* in_sizes, int n_in,
                              void* d_out, int out_size)
{
    const float* emb = (const float*)d_in[0];
    const int*   ei  = (const int*)d_in[1];
    const float* W1  = (const float*)d_in[2];
    const float* b1  = (const float*)d_in[3];
    const float* W2  = (const float*)d_in[4];
    const float* b2  = (const float*)d_in[5];
    float*       out = (float*)d_out;

    const int Hn = in_sizes[3];
    const int N  = in_sizes[0] / Hn;
    const int E  = in_sizes[1] / 2;
    if (Hn != H256 || N > NPAD) return;

    float *gbuf, *ssbuf, *invbuf;
    __nv_bfloat16 *hhi, *hlo, *w1h, *w1l, *w2h, *w2l;
    cudaGetSymbolAddress((void**)&gbuf,  g_g);
    cudaGetSymbolAddress((void**)&hhi,   g_h_hi);
    cudaGetSymbolAddress((void**)&hlo,   g_h_lo);
    cudaGetSymbolAddress((void**)&w1h,   g_w1_hi);
    cudaGetSymbolAddress((void**)&w1l,   g_w1_lo);
    cudaGetSymbolAddress((void**)&w2h,   g_w2_hi);
    cudaGetSymbolAddress((void**)&w2l,   g_w2_lo);
    cudaGetSymbolAddress((void**)&ssbuf, g_sumsq);
    cudaGetSymbolAddress((void**)&invbuf, g_inv);

    cudaFuncSetAttribute(gemm_hmma, cudaFuncAttributeMaxDynamicSharedMemorySize, SMEM_BYTES);

    prep_w<<<(H256 * H256 + 255) / 256, 256>>>(W1, W2, w1h, w1l, w2h, w2l, ssbuf);

    dim3 ggrid(NPAD / 128, 2);
    // Layer 1: h = relu(emb @ W1^T + b1), emb split on the fly, h stored split
    gemm_hmma<<<ggrid, 256, SMEM_BYTES>>>(emb, nullptr, nullptr, w1h, w1l, b1, N, 0,
                                          hhi, hlo, nullptr, nullptr);
    // Layer 2: g = h @ W2^T + b2 (fp32) + fused row sumsq
    gemm_hmma<<<ggrid, 256, SMEM_BYTES>>>(nullptr, hhi, hlo, w2h, w2l, b2, N, 1,
                                          nullptr, nullptr, gbuf, ssbuf);
    finish_inv<<<(NPAD + 255) / 256, 256>>>(ssbuf, invbuf, NPAD);
    edge_kernel<<<(E + 7) / 8, 256>>>(gbuf, invbuf, ei, out, E, N);
}

// round 8
// speedup vs baseline: 2.3879x; 1.1508x over previous
#include <cuda_runtime.h>
#include <cuda_bf16.h>
#include <cstdint>
#include <math.h>

// N=50000, H=256, E=300000.
// g = MLP(emb) once over nodes (exact restructure), per-edge cosine gather.
// GEMMs: warp-level HMMA (mma.sync bf16) — tcgen05 unavailable (harness
// compiles compute_103 without 'a' features). Split precision 3-product.
// This round: 64x128 tiles, 96KB smem, 2 CTAs/SM, inv-norm fused into edges.

#define H256 256
#define NPAD 50176  // 784*64

// ---------------- device scratch (allocation-free) ----------------
__device__ __align__(16) float          g_g[(size_t)NPAD * H256];
__device__ __align__(16) __nv_bfloat16  g_h_hi[(size_t)NPAD * H256];
__device__ __align__(16) __nv_bfloat16  g_h_lo[(size_t)NPAD * H256];
__device__ __align__(16) __nv_bfloat16  g_w1_hi[H256 * H256];
__device__ __align__(16) __nv_bfloat16  g_w1_lo[H256 * H256];
__device__ __align__(16) __nv_bfloat16  g_w2_hi[H256 * H256];
__device__ __align__(16) __nv_bfloat16  g_w2_lo[H256 * H256];
__device__ float g_sumsq[NPAD];

// ---------------- PTX helpers ----------------
__device__ __forceinline__ uint32_t smem_u32(const void* p) {
    uint32_t a;
    asm("{ .reg .u64 t; cvta.to.shared.u64 t, %1; cvt.u32.u64 %0, t; }" : "=r"(a) : "l"(p));
    return a;
}
__device__ __forceinline__ void cp16(uint32_t s, const void* g) {
    asm volatile("cp.async.cg.shared.global [%0], [%1], 16;"
                 :: "r"(s), "l"(__cvta_generic_to_global(g)) : "memory");
}
__device__ __forceinline__ void cp_commit() {
    asm volatile("cp.async.commit_group;" ::: "memory");
}
template <int NN>
__device__ __forceinline__ void cp_wait() {
    asm volatile("cp.async.wait_group %0;" :: "n"(NN) : "memory");
}
__device__ __forceinline__ void ldsm4(uint32_t* r, uint32_t addr) {
    asm volatile("ldmatrix.sync.aligned.m8n8.x4.shared.b16 {%0,%1,%2,%3}, [%4];"
                 : "=r"(r[0]), "=r"(r[1]), "=r"(r[2]), "=r"(r[3]) : "r"(addr));
}
__device__ __forceinline__ void mma_bf16(float* c, const uint32_t* a, const uint32_t* b) {
    asm volatile(
        "mma.sync.aligned.m16n8k16.row.col.f32.bf16.bf16.f32 "
        "{%0,%1,%2,%3}, {%4,%5,%6,%7}, {%8,%9}, {%0,%1,%2,%3};"
        : "+f"(c[0]), "+f"(c[1]), "+f"(c[2]), "+f"(c[3])
        : "r"(a[0]), "r"(a[1]), "r"(a[2]), "r"(a[3]), "r"(b[0]), "r"(b[1]));
}
__device__ __forceinline__ uint32_t pack_bf2(float a, float b) {
    __nv_bfloat162 t = __floats2bfloat162_rn(a, b);
    return *reinterpret_cast<uint32_t*>(&t);
}

// SMEM (per-CTA 96KB):
//  A stage st (st=0,1): base st*16384; hi at +0 (8KB: 64r x 64k bf16), lo +8192
//  B stage st: base 32768 + st*32768; hi +0 (16KB: 128r x 64k), lo +16384
#define A_ST(st)  ((uint32_t)(st) * 16384u)
#define B_ST(st)  (32768u + (uint32_t)(st) * 32768u)
#define SMEM_BYTES 98304

// ---------------------------------------------------------------------------
// HMMA split-bf16 GEMM: C[64,128] tile/CTA, 256 thr (8 warps, 2m x 4n, 32x32).
// K=256 in 4 chunks of 64; A and B chunk-double-buffered. 2 CTAs/SM.
// mode 0: A = fp32 (split on the fly, reg-staged); out = relu(C+bias) split.
// mode 1: A = bf16 hi/lo (cp.async); out = fp32 C+bias + fused row sumsq.
// ---------------------------------------------------------------------------
__global__ __launch_bounds__(256, 2) void gemm_hmma(
    const float* __restrict__ A32,
    const __nv_bfloat16* __restrict__ Ahi, const __nv_bfloat16* __restrict__ Alo,
    const __nv_bfloat16* __restrict__ Bhi, const __nv_bfloat16* __restrict__ Blo,
    const float* __restrict__ bias, int Nn, int mode,
    __nv_bfloat16* __restrict__ OutHi, __nv_bfloat16* __restrict__ OutLo,
    float* __restrict__ OutF, float* __restrict__ sumsq)
{
    extern __shared__ char smem[];
    const uint32_t sb = smem_u32(smem);
    const int tid  = threadIdx.x;
    const int lane = tid & 31, wid = tid >> 5;
    const int wm = wid & 1, wn = wid >> 1;        // 2 x 4 warp grid (32x32 tiles)
    const int row0 = blockIdx.x * 64;
    const int col0 = blockIdx.y * 128;

    float C[2][4][4];
#pragma unroll
    for (int i = 0; i < 2; i++)
#pragma unroll
        for (int j = 0; j < 4; j++)
#pragma unroll
            for (int q = 0; q < 4; q++) C[i][j][q] = 0.0f;

    // ---- ldmatrix lane addressing ----
    const int a_r  = wm * 32 + (lane & 7) + ((lane >> 3) & 1) * 8;
    const int a_kq = ((lane >> 4) & 1) * 8;
    const int b_n  = wn * 32 + (lane & 7) + ((lane >> 4) & 1) * 8;
    const int b_kq = ((lane >> 3) & 1) * 8;
    uint32_t aRow[2], aMask[2], bRow[2], bMask[2];
#pragma unroll
    for (int i = 0; i < 2; i++) {
        int r = a_r + i * 16;
        aRow[i]  = (uint32_t)(r * 128);
        aMask[i] = (uint32_t)((r & 7) << 4);
    }
#pragma unroll
    for (int j = 0; j < 2; j++) {
        int n = b_n + j * 16;
        bRow[j]  = (uint32_t)(n * 128);
        bMask[j] = (uint32_t)((n & 7) << 4);
    }

    // ---- loader helpers ----
    auto loadB = [&](int kc, int st) {
        uint32_t bh = sb + B_ST(st), bl = bh + 16384u;
#pragma unroll
        for (int it = 0; it < 4; it++) {
            int idx = tid + it * 256;          // 0..1023
            int r = idx >> 3, c8 = idx & 7;
            uint32_t off = (uint32_t)(r * 128 + ((c8 * 16) ^ ((r & 7) << 4)));
            size_t gofs = (size_t)(col0 + r) * H256 + kc * 64 + c8 * 8;
            cp16(bh + off, Bhi + gofs);
            cp16(bl + off, Blo + gofs);
        }
    };
    auto loadA1 = [&](int kc, int st) {        // mode 1: bf16 split via cp.async
        uint32_t ah = sb + A_ST(st), al = ah + 8192u;
#pragma unroll
        for (int it = 0; it < 2; it++) {
            int idx = tid + it * 256;          // 0..511
            int r = idx >> 3, c8 = idx & 7;
            uint32_t off = (uint32_t)(r * 128 + ((c8 * 16) ^ ((r & 7) << 4)));
            size_t gofs = (size_t)(row0 + r) * H256 + kc * 64 + c8 * 8;
            cp16(ah + off, Ahi + gofs);
            cp16(al + off, Alo + gofs);
        }
    };

    float4 regs[4];
    auto fetchA0 = [&](int kc) {               // mode 0: fp32 -> regs (guarded)
#pragma unroll
        for (int it = 0; it < 4; it++) {
            int idx = tid + it * 256;          // 0..1023 float4 units
            int r = idx >> 4, k4u = idx & 15;
            regs[it] = (row0 + r < Nn)
                ? *(const float4*)(A32 + (size_t)(row0 + r) * H256 + kc * 64 + k4u * 4)
                : make_float4(0.f, 0.f, 0.f, 0.f);
        }
    };
    auto storeA0 = [&](int st) {               // regs -> split bf16 smem
        const uint32_t base = A_ST(st);
#pragma unroll
        for (int it = 0; it < 4; it++) {
            int idx = tid + it * 256;
            int r = idx >> 4, k4u = idx & 15;
            float4 v = regs[it];
            float h0 = __bfloat162float(__float2bfloat16_rn(v.x));
            float h1 = __bfloat162float(__float2bfloat16_rn(v.y));
            float h2 = __bfloat162float(__float2bfloat16_rn(v.z));
            float h3 = __bfloat162float(__float2bfloat16_rn(v.w));
            uint32_t off = (uint32_t)(r * 128 + ((k4u * 8) ^ ((r & 7) << 4)));
            *(uint2*)(smem + base + off) = make_uint2(pack_bf2(h0, h1), pack_bf2(h2, h3));
            *(uint2*)(smem + base + 8192 + off) =
                make_uint2(pack_bf2(v.x - h0, v.y - h1), pack_bf2(v.z - h2, v.w - h3));
        }
    };

    // ---- prologue: chunk 0 in flight ----
    loadB(0, 0);
    if (mode == 1) loadA1(0, 0);
    cp_commit();
    if (mode == 0) fetchA0(0);

#pragma unroll
    for (int kc = 0; kc < 4; kc++) {
        const int st = kc & 1;
        if (mode == 0) storeA0(st);            // safe: stage st idle since sync(kc-1)
        cp_wait<0>();                          // chunk kc async loads arrived
        __syncthreads();                       // all warps done MMA(kc-1)
        if (kc < 3) {                          // next chunk into the other stage
            loadB(kc + 1, st ^ 1);
            if (mode == 1) loadA1(kc + 1, st ^ 1);
            cp_commit();
            if (mode == 0) fetchA0(kc + 1);    // global->regs overlaps MMA
        }

        const uint32_t aH = sb + A_ST(st), aL = aH + 8192u;
        const uint32_t bH = sb + B_ST(st), bL = bH + 16384u;
#pragma unroll
        for (int s = 0; s < 4; s++) {
            const int k0 = s * 16;
            uint32_t ah[2][4], al[2][4], bh[2][4], bl[2][4];
#pragma unroll
            for (int i = 0; i < 2; i++) {
                uint32_t off = aRow[i] + (((uint32_t)((k0 + a_kq) * 2)) ^ aMask[i]);
                ldsm4(ah[i], aH + off);
                ldsm4(al[i], aL + off);
            }
#pragma unroll
            for (int j = 0; j < 2; j++) {
                uint32_t off = bRow[j] + (((uint32_t)((k0 + b_kq) * 2)) ^ bMask[j]);
                ldsm4(bh[j], bH + off);
                ldsm4(bl[j], bL + off);
            }
#pragma unroll
            for (int i = 0; i < 2; i++)
#pragma unroll
                for (int j = 0; j < 2; j++)
#pragma unroll
                    for (int h = 0; h < 2; h++) {
                        const int ns = j * 2 + h;
                        mma_bf16(C[i][ns], ah[i], &bh[j][2 * h]);
                        mma_bf16(C[i][ns], ah[i], &bl[j][2 * h]);
                        mma_bf16(C[i][ns], al[i], &bh[j][2 * h]);
                    }
        }
    }

    // ---- Epilogue ----
    const int rbase = row0 + wm * 32 + (lane >> 2);
    const int cbase = col0 + wn * 32 + (lane & 3) * 2;
    float ss[2][2] = {{0.f, 0.f}, {0.f, 0.f}};

#pragma unroll
    for (int i = 0; i < 2; i++) {
#pragma unroll
        for (int ns = 0; ns < 4; ns++) {
            const int c   = cbase + ns * 8;
            const float bv0 = __ldg(&bias[c]);
            const float bv1 = __ldg(&bias[c + 1]);
#pragma unroll
            for (int rh = 0; rh < 2; rh++) {
                const int r = rbase + i * 16 + rh * 8;
                float v0 = C[i][ns][rh * 2 + 0] + bv0;
                float v1 = C[i][ns][rh * 2 + 1] + bv1;
                const size_t go = (size_t)r * H256 + c;
                if (mode == 0) {
                    v0 = fmaxf(v0, 0.0f);
                    v1 = fmaxf(v1, 0.0f);
                    float h0 = __bfloat162float(__float2bfloat16_rn(v0));
                    float h1 = __bfloat162float(__float2bfloat16_rn(v1));
                    *(uint32_t*)(OutHi + go) = pack_bf2(h0, h1);
                    *(uint32_t*)(OutLo + go) = pack_bf2(v0 - h0, v1 - h1);
                } else {
                    *(float2*)(OutF + go) = make_float2(v0, v1);
                    ss[i][rh] = fmaf(v0, v0, ss[i][rh]);
                    ss[i][rh] = fmaf(v1, v1, ss[i][rh]);
                }
            }
        }
    }

    if (mode == 1) {
        // Deterministic in-CTA row reduction; one atomicAdd per row per CTA
        // (exactly 2 commutative contributors per row across blockIdx.y).
        __syncthreads();                       // MMA readers done; reuse smem
        float* red = (float*)smem;             // 64 rows x 4 (wn)
#pragma unroll
        for (int i = 0; i < 2; i++)
#pragma unroll
            for (int rh = 0; rh < 2; rh++) {
                float s = ss[i][rh];
                s += __shfl_xor_sync(0xffffffffu, s, 1);
                s += __shfl_xor_sync(0xffffffffu, s, 2);
                int rl = wm * 32 + (lane >> 2) + i * 16 + rh * 8;
                if ((lane & 3) == 0) red[rl * 4 + wn] = s;
            }
        __syncthreads();
        if (tid < 64) {
            float s = ((red[tid * 4] + red[tid * 4 + 1]) + red[tid * 4 + 2]) + red[tid * 4 + 3];
            atomicAdd(&sumsq[row0 + tid], s);
        }
    }
}

// ---------------------------------------------------------------------------
// Prep: split W1/W2 into bf16 hi/lo; zero sumsq.
// ---------------------------------------------------------------------------
__global__ __launch_bounds__(256) void prep_w(
    const float* __restrict__ W1, const float* __restrict__ W2,
    __nv_bfloat16* w1h, __nv_bfloat16* w1l,
    __nv_bfloat16* w2h, __nv_bfloat16* w2l, float* ss)
{
    int i = blockIdx.x * 256 + threadIdx.x;
    if (i < H256 * H256) {
        float a = W1[i];
        __nv_bfloat16 h = __float2bfloat16_rn(a);
        w1h[i] = h;
        w1l[i] = __float2bfloat16_rn(a - __bfloat162float(h));
        float b = W2[i];
        __nv_bfloat16 h2 = __float2bfloat16_rn(b);
        w2h[i] = h2;
        w2l[i] = __float2bfloat16_rn(b - __bfloat162float(h2));
    }
    if (i < NPAD) ss[i] = 0.0f;
}

// ---------------------------------------------------------------------------
// Edge kernel: one warp per edge; g rows L2-resident (51 MB). Inverse-norm
// computed inline from sumsq (kills the finish_inv launch).
// ---------------------------------------------------------------------------
__global__ __launch_bounds__(256) void edge_kernel(
    const float* __restrict__ g, const float* __restrict__ ssq,
    const int* __restrict__ ei, float* __restrict__ out, int E, int N)
{
    int e    = blockIdx.x * 8 + (threadIdx.x >> 5);
    int lane = threadIdx.x & 31;
    if (e >= E) return;
    int c = ei[e];
    int r = ei[E + e];
    c = min(max(c, 0), N - 1);
    r = min(max(r, 0), N - 1);
    const float4* p1 = (const float4*)(g + (size_t)c * H256);
    const float4* p2 = (const float4*)(g + (size_t)r * H256);
    float s = 0.0f;
#pragma unroll
    for (int i = 0; i < 2; i++) {
        float4 a = p1[lane + i * 32];
        float4 b = p2[lane + i * 32];
        s = fmaf(a.x, b.x, s); s = fmaf(a.y, b.y, s);
        s = fmaf(a.z, b.z, s); s = fmaf(a.w, b.w, s);
    }
#pragma unroll
    for (int o = 16; o; o >>= 1) s += __shfl_xor_sync(0xffffffffu, s, o);
    if (lane == 0) {
        float nc = fmaxf(sqrtf(ssq[c]), 1e-8f);
        float nr = fmaxf(sqrtf(ssq[r]), 1e-8f);
        out[e] = s / (nc * nr);
    }
}

// ---------------------------------------------------------------------------
extern "C" void kernel_launch(void* const* d_in, const int* in_sizes, int n_in,
                              void* d_out, int out_size)
{
    const float* emb = (const float*)d_in[0];
    const int*   ei  = (const int*)d_in[1];
    const float* W1  = (const float*)d_in[2];
    const float* b1  = (const float*)d_in[3];
    const float* W2  = (const float*)d_in[4];
    const float* b2  = (const float*)d_in[5];
    float*       out = (float*)d_out;

    const int Hn = in_sizes[3];
    const int N  = in_sizes[0] / Hn;
    const int E  = in_sizes[1] / 2;
    if (Hn != H256 || N > NPAD) return;

    float *gbuf, *ssbuf;
    __nv_bfloat16 *hhi, *hlo, *w1h, *w1l, *w2h, *w2l;
    cudaGetSymbolAddress((void**)&gbuf,  g_g);
    cudaGetSymbolAddress((void**)&hhi,   g_h_hi);
    cudaGetSymbolAddress((void**)&hlo,   g_h_lo);
    cudaGetSymbolAddress((void**)&w1h,   g_w1_hi);
    cudaGetSymbolAddress((void**)&w1l,   g_w1_lo);
    cudaGetSymbolAddress((void**)&w2h,   g_w2_hi);
    cudaGetSymbolAddress((void**)&w2l,   g_w2_lo);
    cudaGetSymbolAddress((void**)&ssbuf, g_sumsq);

    cudaFuncSetAttribute(gemm_hmma, cudaFuncAttributeMaxDynamicSharedMemorySize, SMEM_BYTES);

    prep_w<<<(H256 * H256 + 255) / 256, 256>>>(W1, W2, w1h, w1l, w2h, w2l, ssbuf);

    dim3 ggrid(NPAD / 64, 2);
    // Layer 1: h = relu(emb @ W1^T + b1), emb split on the fly, h stored split
    gemm_hmma<<<ggrid, 256, SMEM_BYTES>>>(emb, nullptr, nullptr, w1h, w1l, b1, N, 0,
                                          hhi, hlo, nullptr, nullptr);
    // Layer 2: g = h @ W2^T + b2 (fp32) + fused row sumsq
    gemm_hmma<<<ggrid, 256, SMEM_BYTES>>>(nullptr, hhi, hlo, w2h, w2l, b2, N, 1,
                                          nullptr, nullptr, gbuf, ssbuf);
    edge_kernel<<<(E + 7) / 8, 256>>>(gbuf, ssbuf, ei, out, E, N);
}

// round 9
// speedup vs baseline: 2.5033x; 1.0483x over previous
#include <cuda_runtime.h>
#include <cuda_bf16.h>
#include <cuda_fp16.h>
#include <cstdint>
#include <math.h>

// N=50000, H=256, E=300000.
// g = MLP(emb) once over nodes (exact restructure), per-edge cosine gather.
// GEMMs: warp-level HMMA (mma.sync bf16; tcgen05 unavailable on this
// harness's compute_103 target). Split precision 3-product.
// This round: normalized fp16 gather table (halves edge traffic), sumsq via
// two part-arrays (no atomics, no zero-init), prep touches weights only.

#define H256 256
#define NPAD 50176  // 784*64

// ---------------- device scratch (allocation-free) ----------------
__device__ __align__(16) float          g_g[(size_t)NPAD * H256];
__device__ __align__(16) __half         g_ghat[(size_t)NPAD * H256];  // normalized fp16
__device__ __align__(16) __nv_bfloat16  g_h_hi[(size_t)NPAD * H256];
__device__ __align__(16) __nv_bfloat16  g_h_lo[(size_t)NPAD * H256];
__device__ __align__(16) __nv_bfloat16  g_w1_hi[H256 * H256];
__device__ __align__(16) __nv_bfloat16  g_w1_lo[H256 * H256];
__device__ __align__(16) __nv_bfloat16  g_w2_hi[H256 * H256];
__device__ __align__(16) __nv_bfloat16  g_w2_lo[H256 * H256];
__device__ float g_sumsq[2 * NPAD];     // per-column-tile partial row sumsq

// ---------------- PTX helpers ----------------
__device__ __forceinline__ uint32_t smem_u32(const void* p) {
    uint32_t a;
    asm("{ .reg .u64 t; cvta.to.shared.u64 t, %1; cvt.u32.u64 %0, t; }" : "=r"(a) : "l"(p));
    return a;
}
__device__ __forceinline__ void cp16(uint32_t s, const void* g) {
    asm volatile("cp.async.cg.shared.global [%0], [%1], 16;"
                 :: "r"(s), "l"(__cvta_generic_to_global(g)) : "memory");
}
__device__ __forceinline__ void cp_commit() {
    asm volatile("cp.async.commit_group;" ::: "memory");
}
template <int NN>
__device__ __forceinline__ void cp_wait() {
    asm volatile("cp.async.wait_group %0;" :: "n"(NN) : "memory");
}
__device__ __forceinline__ void ldsm4(uint32_t* r, uint32_t addr) {
    asm volatile("ldmatrix.sync.aligned.m8n8.x4.shared.b16 {%0,%1,%2,%3}, [%4];"
                 : "=r"(r[0]), "=r"(r[1]), "=r"(r[2]), "=r"(r[3]) : "r"(addr));
}
__device__ __forceinline__ void mma_bf16(float* c, const uint32_t* a, const uint32_t* b) {
    asm volatile(
        "mma.sync.aligned.m16n8k16.row.col.f32.bf16.bf16.f32 "
        "{%0,%1,%2,%3}, {%4,%5,%6,%7}, {%8,%9}, {%0,%1,%2,%3};"
        : "+f"(c[0]), "+f"(c[1]), "+f"(c[2]), "+f"(c[3])
        : "r"(a[0]), "r"(a[1]), "r"(a[2]), "r"(a[3]), "r"(b[0]), "r"(b[1]));
}
__device__ __forceinline__ uint32_t pack_bf2(float a, float b) {
    __nv_bfloat162 t = __floats2bfloat162_rn(a, b);
    return *reinterpret_cast<uint32_t*>(&t);
}

// SMEM (per-CTA 96KB):
//  A stage st: base st*16384; hi +0 (8KB: 64r x 64k bf16), lo +8192
//  B stage st: base 32768 + st*32768; hi +0 (16KB: 128r x 64k), lo +16384
#define A_ST(st)  ((uint32_t)(st) * 16384u)
#define B_ST(st)  (32768u + (uint32_t)(st) * 32768u)
#define SMEM_BYTES 98304

// ---------------------------------------------------------------------------
// HMMA split-bf16 GEMM: C[64,128] tile/CTA, 256 thr (8 warps, 2m x 4n, 32x32).
// K=256 in 4 chunks of 64; A and B chunk-double-buffered. 2 CTAs/SM.
// mode 0: A = fp32 (split on the fly, reg-staged); out = relu(C+bias) split.
// mode 1: A = bf16 hi/lo (cp.async); out = fp32 C+bias + row sumsq part.
// ---------------------------------------------------------------------------
__global__ __launch_bounds__(256, 2) void gemm_hmma(
    const float* __restrict__ A32,
    const __nv_bfloat16* __restrict__ Ahi, const __nv_bfloat16* __restrict__ Alo,
    const __nv_bfloat16* __restrict__ Bhi, const __nv_bfloat16* __restrict__ Blo,
    const float* __restrict__ bias, int Nn, int mode,
    __nv_bfloat16* __restrict__ OutHi, __nv_bfloat16* __restrict__ OutLo,
    float* __restrict__ OutF, float* __restrict__ sumsq)
{
    extern __shared__ char smem[];
    const uint32_t sb = smem_u32(smem);
    const int tid  = threadIdx.x;
    const int lane = tid & 31, wid = tid >> 5;
    const int wm = wid & 1, wn = wid >> 1;        // 2 x 4 warp grid (32x32 tiles)
    const int row0 = blockIdx.x * 64;
    const int col0 = blockIdx.y * 128;

    float C[2][4][4];
#pragma unroll
    for (int i = 0; i < 2; i++)
#pragma unroll
        for (int j = 0; j < 4; j++)
#pragma unroll
            for (int q = 0; q < 4; q++) C[i][j][q] = 0.0f;

    // ---- ldmatrix lane addressing ----
    const int a_r  = wm * 32 + (lane & 7) + ((lane >> 3) & 1) * 8;
    const int a_kq = ((lane >> 4) & 1) * 8;
    const int b_n  = wn * 32 + (lane & 7) + ((lane >> 4) & 1) * 8;
    const int b_kq = ((lane >> 3) & 1) * 8;
    uint32_t aRow[2], aMask[2], bRow[2], bMask[2];
#pragma unroll
    for (int i = 0; i < 2; i++) {
        int r = a_r + i * 16;
        aRow[i]  = (uint32_t)(r * 128);
        aMask[i] = (uint32_t)((r & 7) << 4);
    }
#pragma unroll
    for (int j = 0; j < 2; j++) {
        int n = b_n + j * 16;
        bRow[j]  = (uint32_t)(n * 128);
        bMask[j] = (uint32_t)((n & 7) << 4);
    }

    // ---- loader helpers ----
    auto loadB = [&](int kc, int st) {
        uint32_t bh = sb + B_ST(st), bl = bh + 16384u;
#pragma unroll
        for (int it = 0; it < 4; it++) {
            int idx = tid + it * 256;          // 0..1023
            int r = idx >> 3, c8 = idx & 7;
            uint32_t off = (uint32_t)(r * 128 + ((c8 * 16) ^ ((r & 7) << 4)));
            size_t gofs = (size_t)(col0 + r) * H256 + kc * 64 + c8 * 8;
            cp16(bh + off, Bhi + gofs);
            cp16(bl + off, Blo + gofs);
        }
    };
    auto loadA1 = [&](int kc, int st) {        // mode 1: bf16 split via cp.async
        uint32_t ah = sb + A_ST(st), al = ah + 8192u;
#pragma unroll
        for (int it = 0; it < 2; it++) {
            int idx = tid + it * 256;          // 0..511
            int r = idx >> 3, c8 = idx & 7;
            uint32_t off = (uint32_t)(r * 128 + ((c8 * 16) ^ ((r & 7) << 4)));
            size_t gofs = (size_t)(row0 + r) * H256 + kc * 64 + c8 * 8;
            cp16(ah + off, Ahi + gofs);
            cp16(al + off, Alo + gofs);
        }
    };

    float4 regs[4];
    auto fetchA0 = [&](int kc) {               // mode 0: fp32 -> regs (guarded)
#pragma unroll
        for (int it = 0; it < 4; it++) {
            int idx = tid + it * 256;          // 0..1023 float4 units
            int r = idx >> 4, k4u = idx & 15;
            regs[it] = (row0 + r < Nn)
                ? *(const float4*)(A32 + (size_t)(row0 + r) * H256 + kc * 64 + k4u * 4)
                : make_float4(0.f, 0.f, 0.f, 0.f);
        }
    };
    auto storeA0 = [&](int st) {               // regs -> split bf16 smem
        const uint32_t base = A_ST(st);
#pragma unroll
        for (int it = 0; it < 4; it++) {
            int idx = tid + it * 256;
            int r = idx >> 4, k4u = idx & 15;
            float4 v = regs[it];
            float h0 = __bfloat162float(__float2bfloat16_rn(v.x));
            float h1 = __bfloat162float(__float2bfloat16_rn(v.y));
            float h2 = __bfloat162float(__float2bfloat16_rn(v.z));
            float h3 = __bfloat162float(__float2bfloat16_rn(v.w));
            uint32_t off = (uint32_t)(r * 128 + ((k4u * 8) ^ ((r & 7) << 4)));
            *(uint2*)(smem + base + off) = make_uint2(pack_bf2(h0, h1), pack_bf2(h2, h3));
            *(uint2*)(smem + base + 8192 + off) =
                make_uint2(pack_bf2(v.x - h0, v.y - h1), pack_bf2(v.z - h2, v.w - h3));
        }
    };

    // ---- prologue: chunk 0 in flight ----
    loadB(0, 0);
    if (mode == 1) loadA1(0, 0);
    cp_commit();
    if (mode == 0) fetchA0(0);

#pragma unroll
    for (int kc = 0; kc < 4; kc++) {
        const int st = kc & 1;
        if (mode == 0) storeA0(st);            // safe: stage st idle since sync(kc-1)
        cp_wait<0>();                          // chunk kc async loads arrived
        __syncthreads();                       // all warps done MMA(kc-1)
        if (kc < 3) {                          // next chunk into the other stage
            loadB(kc + 1, st ^ 1);
            if (mode == 1) loadA1(kc + 1, st ^ 1);
            cp_commit();
            if (mode == 0) fetchA0(kc + 1);    // global->regs overlaps MMA
        }

        const uint32_t aH = sb + A_ST(st), aL = aH + 8192u;
        const uint32_t bH = sb + B_ST(st), bL = bH + 16384u;
#pragma unroll
        for (int s = 0; s < 4; s++) {
            const int k0 = s * 16;
            uint32_t ah[2][4], al[2][4], bh[2][4], bl[2][4];
#pragma unroll
            for (int i = 0; i < 2; i++) {
                uint32_t off = aRow[i] + (((uint32_t)((k0 + a_kq) * 2)) ^ aMask[i]);
                ldsm4(ah[i], aH + off);
                ldsm4(al[i], aL + off);
            }
#pragma unroll
            for (int j = 0; j < 2; j++) {
                uint32_t off = bRow[j] + (((uint32_t)((k0 + b_kq) * 2)) ^ bMask[j]);
                ldsm4(bh[j], bH + off);
                ldsm4(bl[j], bL + off);
            }
#pragma unroll
            for (int i = 0; i < 2; i++)
#pragma unroll
                for (int j = 0; j < 2; j++)
#pragma unroll
                    for (int h = 0; h < 2; h++) {
                        const int ns = j * 2 + h;
                        mma_bf16(C[i][ns], ah[i], &bh[j][2 * h]);
                        mma_bf16(C[i][ns], ah[i], &bl[j][2 * h]);
                        mma_bf16(C[i][ns], al[i], &bh[j][2 * h]);
                    }
        }
    }

    // ---- Epilogue ----
    const int rbase = row0 + wm * 32 + (lane >> 2);
    const int cbase = col0 + wn * 32 + (lane & 3) * 2;
    float ss[2][2] = {{0.f, 0.f}, {0.f, 0.f}};

#pragma unroll
    for (int i = 0; i < 2; i++) {
#pragma unroll
        for (int ns = 0; ns < 4; ns++) {
            const int c   = cbase + ns * 8;
            const float bv0 = __ldg(&bias[c]);
            const float bv1 = __ldg(&bias[c + 1]);
#pragma unroll
            for (int rh = 0; rh < 2; rh++) {
                const int r = rbase + i * 16 + rh * 8;
                float v0 = C[i][ns][rh * 2 + 0] + bv0;
                float v1 = C[i][ns][rh * 2 + 1] + bv1;
                const size_t go = (size_t)r * H256 + c;
                if (mode == 0) {
                    v0 = fmaxf(v0, 0.0f);
                    v1 = fmaxf(v1, 0.0f);
                    float h0 = __bfloat162float(__float2bfloat16_rn(v0));
                    float h1 = __bfloat162float(__float2bfloat16_rn(v1));
                    *(uint32_t*)(OutHi + go) = pack_bf2(h0, h1);
                    *(uint32_t*)(OutLo + go) = pack_bf2(v0 - h0, v1 - h1);
                } else {
                    *(float2*)(OutF + go) = make_float2(v0, v1);
                    ss[i][rh] = fmaf(v0, v0, ss[i][rh]);
                    ss[i][rh] = fmaf(v1, v1, ss[i][rh]);
                }
            }
        }
    }

    if (mode == 1) {
        // Deterministic in-CTA row reduction; plain store to this column
        // tile's partial array (no atomics needed).
        __syncthreads();                       // MMA readers done; reuse smem
        float* red = (float*)smem;             // 64 rows x 4 (wn)
#pragma unroll
        for (int i = 0; i < 2; i++)
#pragma unroll
            for (int rh = 0; rh < 2; rh++) {
                float s = ss[i][rh];
                s += __shfl_xor_sync(0xffffffffu, s, 1);
                s += __shfl_xor_sync(0xffffffffu, s, 2);
                int rl = wm * 32 + (lane >> 2) + i * 16 + rh * 8;
                if ((lane & 3) == 0) red[rl * 4 + wn] = s;
            }
        __syncthreads();
        if (tid < 64) {
            float s = ((red[tid * 4] + red[tid * 4 + 1]) + red[tid * 4 + 2]) + red[tid * 4 + 3];
            sumsq[(size_t)blockIdx.y * NPAD + row0 + tid] = s;
        }
    }
}

// ---------------------------------------------------------------------------
// Prep: split W1/W2 into bf16 hi/lo.
// ---------------------------------------------------------------------------
__global__ __launch_bounds__(256) void prep_w(
    const float* __restrict__ W1, const float* __restrict__ W2,
    __nv_bfloat16* w1h, __nv_bfloat16* w1l,
    __nv_bfloat16* w2h, __nv_bfloat16* w2l)
{
    int i = blockIdx.x * 256 + threadIdx.x;
    if (i < H256 * H256) {
        float a = W1[i];
        __nv_bfloat16 h = __float2bfloat16_rn(a);
        w1h[i] = h;
        w1l[i] = __float2bfloat16_rn(a - __bfloat162float(h));
        float b = W2[i];
        __nv_bfloat16 h2 = __float2bfloat16_rn(b);
        w2h[i] = h2;
        w2l[i] = __float2bfloat16_rn(b - __bfloat162float(h2));
    }
}

// ---------------------------------------------------------------------------
// Normalize: ghat[r][:] = fp16( g[r][:] / max(||g[r]||, eps) ).
// One warp per row, 8 elems per lane.
// ---------------------------------------------------------------------------
__global__ __launch_bounds__(256) void norm_kernel(
    const float* __restrict__ g, const float* __restrict__ ss,
    __half* __restrict__ ghat, int rows)
{
    int row  = blockIdx.x * 8 + (threadIdx.x >> 5);
    int lane = threadIdx.x & 31;
    if (row >= rows) return;
    float inv = 1.0f / fmaxf(sqrtf(ss[row] + ss[NPAD + row]), 1e-8f);
    const float4* p = (const float4*)(g + (size_t)row * H256 + lane * 8);
    float4 v0 = p[0], v1 = p[1];
    __half2 h[4];
    h[0] = __floats2half2_rn(v0.x * inv, v0.y * inv);
    h[1] = __floats2half2_rn(v0.z * inv, v0.w * inv);
    h[2] = __floats2half2_rn(v1.x * inv, v1.y * inv);
    h[3] = __floats2half2_rn(v1.z * inv, v1.w * inv);
    *(uint4*)(ghat + (size_t)row * H256 + lane * 8) = *(const uint4*)h;
}

// ---------------------------------------------------------------------------
// Edge kernel: one warp per edge; fp16 normalized rows (25 MB, L2-resident).
// out[e] = dot(ghat[col], ghat[row]) in fp32.
// ---------------------------------------------------------------------------
__global__ __launch_bounds__(256) void edge_kernel(
    const __half* __restrict__ ghat, const int* __restrict__ ei,
    float* __restrict__ out, int E, int N)
{
    int e    = blockIdx.x * 8 + (threadIdx.x >> 5);
    int lane = threadIdx.x & 31;
    if (e >= E) return;
    int c = ei[e];
    int r = ei[E + e];
    c = min(max(c, 0), N - 1);
    r = min(max(r, 0), N - 1);
    uint4 a = *(const uint4*)(ghat + (size_t)c * H256 + lane * 8);
    uint4 b = *(const uint4*)(ghat + (size_t)r * H256 + lane * 8);
    const __half2* ha = (const __half2*)&a;
    const __half2* hb = (const __half2*)&b;
    float s = 0.0f;
#pragma unroll
    for (int i = 0; i < 4; i++) {
        float2 fa = __half22float2(ha[i]);
        float2 fb = __half22float2(hb[i]);
        s = fmaf(fa.x, fb.x, s);
        s = fmaf(fa.y, fb.y, s);
    }
#pragma unroll
    for (int o = 16; o; o >>= 1) s += __shfl_xor_sync(0xffffffffu, s, o);
    if (lane == 0) out[e] = s;
}

// ---------------------------------------------------------------------------
extern "C" void kernel_launch(void* const* d_in, const int* in_sizes, int n_in,
                              void* d_out, int out_size)
{
    const float* emb = (const float*)d_in[0];
    const int*   ei  = (const int*)d_in[1];
    const float* W1  = (const float*)d_in[2];
    const float* b1  = (const float*)d_in[3];
    const float* W2  = (const float*)d_in[4];
    const float* b2  = (const float*)d_in[5];
    float*       out = (float*)d_out;

    const int Hn = in_sizes[3];
    const int N  = in_sizes[0] / Hn;
    const int E  = in_sizes[1] / 2;
    if (Hn != H256 || N > NPAD) return;

    float *gbuf, *ssbuf;
    __half* ghat;
    __nv_bfloat16 *hhi, *hlo, *w1h, *w1l, *w2h, *w2l;
    cudaGetSymbolAddress((void**)&gbuf,  g_g);
    cudaGetSymbolAddress((void**)&ghat,  g_ghat);
    cudaGetSymbolAddress((void**)&hhi,   g_h_hi);
    cudaGetSymbolAddress((void**)&hlo,   g_h_lo);
    cudaGetSymbolAddress((void**)&w1h,   g_w1_hi);
    cudaGetSymbolAddress((void**)&w1l,   g_w1_lo);
    cudaGetSymbolAddress((void**)&w2h,   g_w2_hi);
    cudaGetSymbolAddress((void**)&w2l,   g_w2_lo);
    cudaGetSymbolAddress((void**)&ssbuf, g_sumsq);

    cudaFuncSetAttribute(gemm_hmma, cudaFuncAttributeMaxDynamicSharedMemorySize, SMEM_BYTES);

    prep_w<<<(H256 * H256 + 255) / 256, 256>>>(W1, W2, w1h, w1l, w2h, w2l);

    dim3 ggrid(NPAD / 64, 2);
    // Layer 1: h = relu(emb @ W1^T + b1), emb split on the fly, h stored split
    gemm_hmma<<<ggrid, 256, SMEM_BYTES>>>(emb, nullptr, nullptr, w1h, w1l, b1, N, 0,
                                          hhi, hlo, nullptr, nullptr);
    // Layer 2: g = h @ W2^T + b2 (fp32) + row sumsq parts
    gemm_hmma<<<ggrid, 256, SMEM_BYTES>>>(nullptr, hhi, hlo, w2h, w2l, b2, N, 1,
                                          nullptr, nullptr, gbuf, ssbuf);
    // Normalize to fp16 gather table
    norm_kernel<<<NPAD / 8, 256>>>(gbuf, ssbuf, ghat, NPAD);
    // Per-edge cosine = fp16 dot
    edge_kernel<<<(E + 7) / 8, 256>>>(ghat, ei, out, E, N);
}